// round 6
// baseline (speedup 1.0000x reference)
#include <cuda_runtime.h>
#include <cuda_bf16.h>
#include <cstdint>
#include <math.h>

#define LSEQ 4096
#define BATCH 4
#define KD 128
#define DD 512

// ---------------- scratch (no allocation allowed) ----------------
__device__ __nv_bfloat16 g_qh[BATCH * LSEQ * KD];
__device__ __nv_bfloat16 g_ql[BATCH * LSEQ * KD];
__device__ __nv_bfloat16 g_kh[BATCH * LSEQ * KD];
__device__ __nv_bfloat16 g_kl[BATCH * LSEQ * KD];
__device__ __nv_bfloat16 g_vh[(size_t)BATCH * DD * LSEQ];   // [b][d][l]
__device__ __nv_bfloat16 g_vl[(size_t)BATCH * DD * LSEQ];
// P blocked: [b][qt(64)][st(64)][64 rows][64 cols]
__device__ __nv_bfloat16 g_ph[(size_t)BATCH * LSEQ * LSEQ];
__device__ __nv_bfloat16 g_pl[(size_t)BATCH * LSEQ * LSEQ];
__device__ float g_lsum[BATCH * LSEQ];

// ---------------- helpers ----------------
__device__ __forceinline__ uint32_t smem_u32(const void* p) {
    uint32_t a;
    asm("{ .reg .u64 t; cvta.to.shared.u64 t, %1; cvt.u32.u64 %0, t; }" : "=r"(a) : "l"(p));
    return a;
}

#define LDSM4(r, addr) \
    asm volatile("ldmatrix.sync.aligned.m8n8.x4.shared.b16 {%0,%1,%2,%3}, [%4];" \
        : "=r"((r)[0]), "=r"((r)[1]), "=r"((r)[2]), "=r"((r)[3]) : "r"(addr))

#define MMA(d, a, b0, b1) \
    asm volatile("mma.sync.aligned.m16n8k16.row.col.f32.bf16.bf16.f32 " \
        "{%0,%1,%2,%3}, {%4,%5,%6,%7}, {%8,%9}, {%0,%1,%2,%3};" \
        : "+f"((d)[0]), "+f"((d)[1]), "+f"((d)[2]), "+f"((d)[3]) \
        : "r"((a)[0]), "r"((a)[1]), "r"((a)[2]), "r"((a)[3]), "r"(b0), "r"(b1))

#define CP16(dst, src) \
    asm volatile("cp.async.cg.shared.global [%0], [%1], 16;" :: "r"(dst), "l"(src))
#define CP_COMMIT() asm volatile("cp.async.commit_group;" ::: "memory")
#define CP_WAIT1()  asm volatile("cp.async.wait_group 1;" ::: "memory")
#define CP_WAIT0()  asm volatile("cp.async.wait_group 0;" ::: "memory")

__device__ __forceinline__ unsigned short bf16bits(float x) {
    __nv_bfloat16 h = __float2bfloat16(x);
    return *reinterpret_cast<unsigned short*>(&h);
}
__device__ __forceinline__ float bf16val(unsigned short u) {
    __nv_bfloat16 h;
    *reinterpret_cast<unsigned short*>(&h) = u;
    return __bfloat162float(h);
}

// ---------------------------------------------------------------------------
// Projection Q/K: GEMM + bias + L2norm -> split bf16 hi/lo, [b][l][128]
// ---------------------------------------------------------------------------
__global__ __launch_bounds__(128) void proj_qk_kernel(
    const float* __restrict__ X, const float* __restrict__ W,
    const float* __restrict__ bias,
    __nv_bfloat16* __restrict__ outh, __nv_bfloat16* __restrict__ outl)
{
    __shared__ float xs[16][32];
    __shared__ float ws[128][36];
    __shared__ float outs[16][128];

    const int tid = threadIdx.x;
    const int m0 = blockIdx.x * 16;

    float acc[16];
#pragma unroll
    for (int r = 0; r < 16; r++) acc[r] = 0.f;

    for (int ck = 0; ck < 16; ck++) {
        __syncthreads();
        { int row = tid >> 3, c4 = tid & 7;
          *(float4*)&xs[row][c4 * 4] =
              *(const float4*)(X + (size_t)(m0 + row) * 512 + ck * 32 + c4 * 4); }
#pragma unroll
        for (int i = 0; i < 8; i++) {
            int f = tid + 128 * i, row = f >> 3, c4 = f & 7;
            *(float4*)&ws[row][c4 * 4] =
                *(const float4*)(W + (size_t)row * 512 + ck * 32 + c4 * 4);
        }
        __syncthreads();
#pragma unroll
        for (int d4 = 0; d4 < 8; d4++) {
            float4 w4 = *(float4*)&ws[tid][d4 * 4];
#pragma unroll
            for (int r = 0; r < 16; r++) {
                float4 x4 = *(float4*)&xs[r][d4 * 4];
                acc[r] += x4.x * w4.x + x4.y * w4.y + x4.z * w4.z + x4.w * w4.w;
            }
        }
    }

    float bv = bias[tid];
#pragma unroll
    for (int r = 0; r < 16; r++) outs[r][tid] = acc[r] + bv;
    __syncthreads();

    int w = tid >> 5, lane = tid & 31;
#pragma unroll
    for (int r = 0; r < 4; r++) {
        int rowi = w * 4 + r;
        float4 v = *(float4*)&outs[rowi][lane * 4];
        float ss = v.x * v.x + v.y * v.y + v.z * v.z + v.w * v.w;
#pragma unroll
        for (int o = 16; o >= 1; o >>= 1)
            ss += __shfl_xor_sync(0xffffffffu, ss, o);
        float sc = 1.f / fmaxf(sqrtf(ss), 1e-12f);
        int m = m0 + rowi, li = m >> 2, bi = m & 3;
        float f0 = v.x * sc, f1 = v.y * sc, f2 = v.z * sc, f3 = v.w * sc;
        unsigned short h0 = bf16bits(f0), h1 = bf16bits(f1),
                       h2 = bf16bits(f2), h3 = bf16bits(f3);
        unsigned short l0 = bf16bits(f0 - bf16val(h0)), l1 = bf16bits(f1 - bf16val(h1)),
                       l2 = bf16bits(f2 - bf16val(h2)), l3 = bf16bits(f3 - bf16val(h3));
        size_t idx = ((size_t)bi * LSEQ + li) * KD + lane * 4;
        uint2 H = make_uint2((uint32_t)h0 | ((uint32_t)h1 << 16),
                             (uint32_t)h2 | ((uint32_t)h3 << 16));
        uint2 L = make_uint2((uint32_t)l0 | ((uint32_t)l1 << 16),
                             (uint32_t)l2 | ((uint32_t)l3 << 16));
        *(uint2*)&outh[idx] = H;
        *(uint2*)&outl[idx] = L;
    }
}

// ---------------------------------------------------------------------------
// Projection V: GEMM + bias -> split bf16 hi/lo TRANSPOSED [b][d][l]
// ---------------------------------------------------------------------------
__global__ __launch_bounds__(128) void proj_v_kernel(
    const float* __restrict__ X, const float* __restrict__ W,
    const float* __restrict__ bias,
    __nv_bfloat16* __restrict__ outh, __nv_bfloat16* __restrict__ outl)
{
    __shared__ float xs[16][32];
    __shared__ float ws[128][36];
    __shared__ float outs[16][128];

    const int tid = threadIdx.x;
    const int m0 = blockIdx.x * 16;
    const int n0 = blockIdx.y * 128;

    float acc[16];
#pragma unroll
    for (int r = 0; r < 16; r++) acc[r] = 0.f;

    for (int ck = 0; ck < 16; ck++) {
        __syncthreads();
        { int row = tid >> 3, c4 = tid & 7;
          *(float4*)&xs[row][c4 * 4] =
              *(const float4*)(X + (size_t)(m0 + row) * 512 + ck * 32 + c4 * 4); }
#pragma unroll
        for (int i = 0; i < 8; i++) {
            int f = tid + 128 * i, row = f >> 3, c4 = f & 7;
            *(float4*)&ws[row][c4 * 4] =
                *(const float4*)(W + (size_t)(n0 + row) * 512 + ck * 32 + c4 * 4);
        }
        __syncthreads();
#pragma unroll
        for (int d4 = 0; d4 < 8; d4++) {
            float4 w4 = *(float4*)&ws[tid][d4 * 4];
#pragma unroll
            for (int r = 0; r < 16; r++) {
                float4 x4 = *(float4*)&xs[r][d4 * 4];
                acc[r] += x4.x * w4.x + x4.y * w4.y + x4.z * w4.z + x4.w * w4.w;
            }
        }
    }

    float bv = bias[n0 + tid];
#pragma unroll
    for (int r = 0; r < 16; r++) outs[r][tid] = acc[r] + bv;
    __syncthreads();

    int li0 = m0 >> 2;
#pragma unroll
    for (int bb = 0; bb < 4; bb++) {
        float f0 = outs[0 + bb][tid], f1 = outs[4 + bb][tid],
              f2 = outs[8 + bb][tid], f3 = outs[12 + bb][tid];
        unsigned short h0 = bf16bits(f0), h1 = bf16bits(f1),
                       h2 = bf16bits(f2), h3 = bf16bits(f3);
        unsigned short l0 = bf16bits(f0 - bf16val(h0)), l1 = bf16bits(f1 - bf16val(h1)),
                       l2 = bf16bits(f2 - bf16val(h2)), l3 = bf16bits(f3 - bf16val(h3));
        size_t idx = ((size_t)bb * DD + n0 + tid) * LSEQ + li0;
        uint2 H = make_uint2((uint32_t)h0 | ((uint32_t)h1 << 16),
                             (uint32_t)h2 | ((uint32_t)h3 << 16));
        uint2 L = make_uint2((uint32_t)l0 | ((uint32_t)l1 << 16),
                             (uint32_t)l2 | ((uint32_t)l3 << 16));
        *(uint2*)&outh[idx] = H;
        *(uint2*)&outl[idx] = L;
    }
}

// ---------------------------------------------------------------------------
// Phase A: QK + softmax, P materialized. Grid (64 qt, 4 b), 256 thr, 2 CTA/SM.
// Warp: rows 16g (g=w&3), keys 32h (h=w>>2). MMAs round-robin 4 accumulators.
// ---------------------------------------------------------------------------
#define A_KRB 272
#define A_KHL 17408
#define A_KSTG 34816
#define A_SMK 0
#define A_SMP 69632
#define A_PBUF 16384
#define A_TOT 102400

__global__ __launch_bounds__(256, 2) void qk_kernel()
{
    extern __shared__ char smem[];
    const uint32_t sb = smem_u32(smem);
    const int tid = threadIdx.x;
    const int lane = tid & 31;
    const int w = tid >> 5;
    const int qt = blockIdx.x;
    const int b = blockIdx.y;
    const int g = w & 3, h = w >> 2;

    const int rowpat = ((lane >> 3) & 1) * 8 + (lane & 7);
    const int colpat = (lane >> 4) * 8;

    for (int idx = tid; idx < 1024; idx += 256) {
        int r = idx >> 4, ch = idx & 15;
        size_t gofs = ((size_t)b * LSEQ + qt * 64 + r) * KD + ch * 8;
        *(uint4*)(smem + A_SMK + r * A_KRB + ch * 16) = *(const uint4*)(g_qh + gofs);
        *(uint4*)(smem + A_SMK + A_KHL + r * A_KRB + ch * 16) = *(const uint4*)(g_ql + gofs);
    }
    __syncthreads();
    uint32_t qa_h[8][4], qa_l[8][4];
    {
        uint32_t base = sb + A_SMK + (uint32_t)((g * 16 + rowpat) * A_KRB + colpat * 2);
#pragma unroll
        for (int kt = 0; kt < 8; kt++) {
            LDSM4(qa_h[kt], base + kt * 32);
            LDSM4(qa_l[kt], base + A_KHL + kt * 32);
        }
    }
    __syncthreads();

    auto load_k = [&](int st, int stg) {
        size_t kb = ((size_t)b * LSEQ + st * 64) * KD;
        uint32_t kd = sb + A_SMK + stg * A_KSTG;
#pragma unroll
        for (int i = 0; i < 4; i++) {
            int idx = tid + i * 256;
            int r = idx >> 4, ch = idx & 15;
            uint32_t d = kd + r * A_KRB + ch * 16;
            CP16(d, g_kh + kb + (size_t)r * KD + ch * 8);
            CP16(d + A_KHL, g_kl + kb + (size_t)r * KD + ch * 8);
        }
    };

    load_k(0, 0);
    CP_COMMIT();

    float la = 0.f, lb = 0.f;
    const int lr = lane >> 2;

#pragma unroll 1
    for (int st = 0; st < 64; st++) {
        const int stg = st & 1;
        if (st + 1 < 64) { load_k(st + 1, stg ^ 1); CP_COMMIT(); CP_WAIT1(); }
        else             { CP_WAIT0(); }
        __syncthreads();

        const uint32_t kb = sb + A_SMK + stg * A_KSTG
                          + (uint32_t)((h * 32 + rowpat) * A_KRB + colpat * 2);
        float s[4][4];
#pragma unroll
        for (int nt = 0; nt < 4; nt++)
#pragma unroll
            for (int j = 0; j < 4; j++) s[nt][j] = 0.f;

#pragma unroll
        for (int kt = 0; kt < 8; kt++) {
            uint32_t k0h[4], k0l[4], k1h[4], k1l[4];
            LDSM4(k0h, kb + kt * 32);
            LDSM4(k1h, kb + 16 * A_KRB + kt * 32);
            LDSM4(k0l, kb + A_KHL + kt * 32);
            LDSM4(k1l, kb + A_KHL + 16 * A_KRB + kt * 32);
            MMA(s[0], qa_h[kt], k0h[0], k0h[2]);
            MMA(s[1], qa_h[kt], k0h[1], k0h[3]);
            MMA(s[2], qa_h[kt], k1h[0], k1h[2]);
            MMA(s[3], qa_h[kt], k1h[1], k1h[3]);
            MMA(s[0], qa_h[kt], k0l[0], k0l[2]);
            MMA(s[1], qa_h[kt], k0l[1], k0l[3]);
            MMA(s[2], qa_h[kt], k1l[0], k1l[2]);
            MMA(s[3], qa_h[kt], k1l[1], k1l[3]);
            MMA(s[0], qa_l[kt], k0h[0], k0h[2]);
            MMA(s[1], qa_l[kt], k0h[1], k0h[3]);
            MMA(s[2], qa_l[kt], k1h[0], k1h[2]);
            MMA(s[3], qa_l[kt], k1h[1], k1h[3]);
        }

        const uint32_t pbase = sb + A_SMP + stg * A_PBUF;
#pragma unroll
        for (int nt = 0; nt < 4; nt++) {
            float p0 = __expf(fmaf(30.f, s[nt][0], -30.f));
            float p1 = __expf(fmaf(30.f, s[nt][1], -30.f));
            float p2 = __expf(fmaf(30.f, s[nt][2], -30.f));
            float p3 = __expf(fmaf(30.f, s[nt][3], -30.f));
            la += p0 + p1;
            lb += p2 + p3;
            __nv_bfloat162 h01 = __floats2bfloat162_rn(p0, p1);
            __nv_bfloat162 h23 = __floats2bfloat162_rn(p2, p3);
            float r0 = p0 - __bfloat162float(h01.x);
            float r1 = p1 - __bfloat162float(h01.y);
            float r2 = p2 - __bfloat162float(h23.x);
            float r3 = p3 - __bfloat162float(h23.y);
            __nv_bfloat162 l01 = __floats2bfloat162_rn(r0, r1);
            __nv_bfloat162 l23 = __floats2bfloat162_rn(r2, r3);
            uint32_t col2 = (uint32_t)((h * 32 + nt * 8 + (lane & 3) * 2) * 2);
            uint32_t a0 = pbase + (uint32_t)((g * 16 + lr) * 128) + col2;
            uint32_t a1 = pbase + (uint32_t)((g * 16 + lr + 8) * 128) + col2;
            asm volatile("st.shared.b32 [%0], %1;" :: "r"(a0), "r"(*(uint32_t*)&h01));
            asm volatile("st.shared.b32 [%0], %1;" :: "r"(a1), "r"(*(uint32_t*)&h23));
            asm volatile("st.shared.b32 [%0], %1;" :: "r"(a0 + 8192), "r"(*(uint32_t*)&l01));
            asm volatile("st.shared.b32 [%0], %1;" :: "r"(a1 + 8192), "r"(*(uint32_t*)&l23));
        }
        __syncthreads();

        size_t blk = (((size_t)b * 64 + qt) * 64 + st) * 4096;
#pragma unroll
        for (int j = 0; j < 2; j++) {
            int flat = tid + j * 256;
            int r = flat >> 3, c16 = flat & 7;
            uint4 vH = *(uint4*)(smem + (pbase - sb) + r * 128 + c16 * 16);
            uint4 vL = *(uint4*)(smem + (pbase - sb) + 8192 + r * 128 + c16 * 16);
            *(uint4*)(g_ph + blk + r * 64 + c16 * 8) = vH;
            *(uint4*)(g_pl + blk + r * 64 + c16 * 8) = vL;
        }
    }

    la += __shfl_xor_sync(0xffffffffu, la, 1);
    la += __shfl_xor_sync(0xffffffffu, la, 2);
    lb += __shfl_xor_sync(0xffffffffu, lb, 1);
    lb += __shfl_xor_sync(0xffffffffu, lb, 2);
    __syncthreads();
    float* ls = (float*)(smem + A_SMP);
    if ((lane & 3) == 0) {
        ls[(g * 16 + lr) * 2 + h] = la;
        ls[(g * 16 + lr + 8) * 2 + h] = lb;
    }
    __syncthreads();
    if (tid < 64)
        g_lsum[b * LSEQ + qt * 64 + tid] = ls[tid * 2] + ls[tid * 2 + 1];
}

// ---------------------------------------------------------------------------
// Phase B: O = P.V, 2(m)x4(n) warp grid, warp tile 64x64. Pass-interleaved.
// Grid (32 qtiles of 128, 4 b, 2 dh). 256 thr.
// ---------------------------------------------------------------------------
#define B_PRB 144
#define B_PHL 18432
#define B_PSTG 36864
#define B_SMP 0
#define B_VRB 144
#define B_VHL 36864
#define B_VSTG 73728
#define B_SMV 73728
#define B_TOT 221184

__global__ __launch_bounds__(256, 1) void pv_kernel(float* __restrict__ out)
{
    extern __shared__ char smem[];
    const uint32_t sb = smem_u32(smem);
    const int tid = threadIdx.x;
    const int lane = tid & 31;
    const int w = tid >> 5;
    const int qX = blockIdx.x;
    const int b = blockIdx.y;
    const int dh = blockIdx.z;
    const int mw = w & 1;        // m half: rows 64*mw..
    const int nw = w >> 1;       // n quarter: cols 64*nw..

    const int rowpat = ((lane >> 3) & 1) * 8 + (lane & 7);
    const int colpat = (lane >> 4) * 8;

    float O[4][8][4];
#pragma unroll
    for (int mt = 0; mt < 4; mt++)
#pragma unroll
        for (int nj = 0; nj < 8; nj++)
#pragma unroll
            for (int j = 0; j < 4; j++) O[mt][nj][j] = 0.f;

    auto load_chunk = [&](int kc, int stg) {
        size_t blkA = (((size_t)b * 64 + qX * 2) * 64 + kc) * 4096;
        uint32_t pd = sb + B_SMP + stg * B_PSTG;
#pragma unroll
        for (int i = 0; i < 4; i++) {
            int idx = tid + i * 256;
            int r = idx >> 3, c16 = idx & 7;
            size_t src = blkA + ((r < 64) ? (size_t)(r * 64)
                                          : (size_t)(64 * 4096 + (r - 64) * 64)) + c16 * 8;
            uint32_t d = pd + r * B_PRB + c16 * 16;
            CP16(d, g_ph + src);
            CP16(d + B_PHL, g_pl + src);
        }
        size_t vb = ((size_t)b * DD + dh * 256) * LSEQ + kc * 64;
        uint32_t vd = sb + B_SMV + stg * B_VSTG;
#pragma unroll
        for (int i = 0; i < 8; i++) {
            int idx = tid + i * 256;
            int r = idx >> 3, c16 = idx & 7;
            uint32_t d = vd + r * B_VRB + c16 * 16;
            CP16(d, g_vh + vb + (size_t)r * LSEQ + c16 * 8);
            CP16(d + B_VHL, g_vl + vb + (size_t)r * LSEQ + c16 * 8);
        }
    };

    load_chunk(0, 0);
    CP_COMMIT();

#pragma unroll 1
    for (int kc = 0; kc < 64; kc++) {
        const int stg = kc & 1;
        if (kc + 1 < 64) { load_chunk(kc + 1, stg ^ 1); CP_COMMIT(); CP_WAIT1(); }
        else             { CP_WAIT0(); }
        __syncthreads();

        const uint32_t pb = sb + B_SMP + stg * B_PSTG
                          + (uint32_t)((mw * 64 + rowpat) * B_PRB + colpat * 2);
        const uint32_t vbs = sb + B_SMV + stg * B_VSTG
                           + (uint32_t)((nw * 64 + rowpat) * B_VRB + colpat * 2);

#pragma unroll
        for (int kt = 0; kt < 4; kt++) {
            uint32_t ah[4][4], al[4][4], vhf[4][4], vlf[4][4];
#pragma unroll
            for (int mt = 0; mt < 4; mt++) {
                LDSM4(ah[mt], pb + (uint32_t)(mt * 16 * B_PRB + kt * 32));
                LDSM4(al[mt], pb + (uint32_t)(B_PHL + mt * 16 * B_PRB + kt * 32));
            }
#pragma unroll
            for (int nt = 0; nt < 4; nt++) {
                LDSM4(vhf[nt], vbs + (uint32_t)(nt * 16 * B_VRB + kt * 32));
                LDSM4(vlf[nt], vbs + (uint32_t)(B_VHL + nt * 16 * B_VRB + kt * 32));
            }
            // pass 1: Ph * Vh
#pragma unroll
            for (int mt = 0; mt < 4; mt++)
#pragma unroll
                for (int nt = 0; nt < 4; nt++) {
                    MMA(O[mt][2 * nt],     ah[mt], vhf[nt][0], vhf[nt][2]);
                    MMA(O[mt][2 * nt + 1], ah[mt], vhf[nt][1], vhf[nt][3]);
                }
            // pass 2: Ph * Vl
#pragma unroll
            for (int mt = 0; mt < 4; mt++)
#pragma unroll
                for (int nt = 0; nt < 4; nt++) {
                    MMA(O[mt][2 * nt],     ah[mt], vlf[nt][0], vlf[nt][2]);
                    MMA(O[mt][2 * nt + 1], ah[mt], vlf[nt][1], vlf[nt][3]);
                }
            // pass 3: Pl * Vh
#pragma unroll
            for (int mt = 0; mt < 4; mt++)
#pragma unroll
                for (int nt = 0; nt < 4; nt++) {
                    MMA(O[mt][2 * nt],     al[mt], vhf[nt][0], vhf[nt][2]);
                    MMA(O[mt][2 * nt + 1], al[mt], vhf[nt][1], vhf[nt][3]);
                }
        }
        __syncthreads();
    }

    // epilogue: divide by lsum, write [L][B][D]
    const int rbase = qX * 128 + mw * 64 + (lane >> 2);
    const int cbase = dh * 256 + nw * 64 + (lane & 3) * 2;
#pragma unroll
    for (int mt = 0; mt < 4; mt++) {
        int r0 = rbase + mt * 16;
        float inv0 = 1.f / g_lsum[b * LSEQ + r0];
        float inv1 = 1.f / g_lsum[b * LSEQ + r0 + 8];
#pragma unroll
        for (int nj = 0; nj < 8; nj++) {
            int col = cbase + nj * 8;
            float2 o0 = make_float2(O[mt][nj][0] * inv0, O[mt][nj][1] * inv0);
            float2 o1 = make_float2(O[mt][nj][2] * inv1, O[mt][nj][3] * inv1);
            *(float2*)(out + ((size_t)r0 * BATCH + b) * DD + col) = o0;
            *(float2*)(out + ((size_t)(r0 + 8) * BATCH + b) * DD + col) = o1;
        }
    }
}

// ---------------------------------------------------------------------------
extern "C" void kernel_launch(void* const* d_in, const int* in_sizes, int n_in,
                              void* d_out, int out_size)
{
    const float* query = (const float*)d_in[0];
    const float* key   = (const float*)d_in[1];
    const float* value = (const float*)d_in[2];
    const float* WKw   = (const float*)d_in[3];
    const float* WKb   = (const float*)d_in[4];
    const float* WVw   = (const float*)d_in[5];
    const float* WVb   = (const float*)d_in[6];
    float* out = (float*)d_out;
    (void)in_sizes; (void)n_in; (void)out_size;

    void *qh, *ql, *kh, *kl, *vh, *vl;
    cudaGetSymbolAddress(&qh, g_qh); cudaGetSymbolAddress(&ql, g_ql);
    cudaGetSymbolAddress(&kh, g_kh); cudaGetSymbolAddress(&kl, g_kl);
    cudaGetSymbolAddress(&vh, g_vh); cudaGetSymbolAddress(&vl, g_vl);

    cudaFuncSetAttribute(qk_kernel,
                         cudaFuncAttributeMaxDynamicSharedMemorySize, A_TOT);
    cudaFuncSetAttribute(pv_kernel,
                         cudaFuncAttributeMaxDynamicSharedMemorySize, B_TOT);

    dim3 gqk(LSEQ * BATCH / 16);
    proj_qk_kernel<<<gqk, 128>>>(query, WKw, WKb,
                                 (__nv_bfloat16*)qh, (__nv_bfloat16*)ql);
    proj_qk_kernel<<<gqk, 128>>>(key, WKw, WKb,
                                 (__nv_bfloat16*)kh, (__nv_bfloat16*)kl);
    dim3 gv(LSEQ * BATCH / 16, 4);
    proj_v_kernel<<<gv, 128>>>(value, WVw, WVb,
                               (__nv_bfloat16*)vh, (__nv_bfloat16*)vl);

    dim3 ga(LSEQ / 64, BATCH);
    qk_kernel<<<ga, 256, A_TOT>>>();
    dim3 gb(LSEQ / 128, BATCH, 2);
    pv_kernel<<<gb, 256, B_TOT>>>(out);
}